// round 15
// baseline (speedup 1.0000x reference)
#include <cuda_runtime.h>
#include <cuda_bf16.h>
#include <cstdint>
#include <cstddef>

#define L     1024
#define DM    256
#define DI    512
#define DS    16
#define RK    16
#define NSEQ  4
#define ROWS  (NSEQ*L)      // 4096
#define CH    32
#define CLEN  (L/CH)        // 32

typedef unsigned long long ull;

// ---------------- device scratch ----------------
__device__ float g_a1[ROWS*DM];          // inter-layer activation
__device__ float g_xz[ROWS*2*DI];        // in_proj output (xc | z)
__device__ float g_xc[ROWS*DI];          // conv+silu output
__device__ float g_dblp[2][ROWS*48];     // x_proj partial outputs (k-split)
__device__ float g_dt[ROWS*DI];          // softplus dt
__device__ float g_y[ROWS*DI];           // gated scan output
__device__ float g_P[NSEQ*DI*CH*DS];     // per-chunk decay
__device__ float g_H[NSEQ*DI*CH*DS];     // per-chunk end state -> init state
__device__ float g_A2[4*DI*DS];          // precomputed -exp(A_log)*log2e
// bf16 split buffers
__device__ __nv_bfloat16 g_Ah[ROWS*512], g_Al[ROWS*512];
__device__ __nv_bfloat16 g_Wih[4*1024*256], g_Wil[4*1024*256];
__device__ __nv_bfloat16 g_Woh[4*256*512], g_Wol[4*256*512];

// ---------------- helpers ----------------
__device__ __forceinline__ ull pk2(float x, float y){
    ull r; asm("mov.b64 %0, {%1, %2};" : "=l"(r) : "f"(x), "f"(y)); return r;
}
__device__ __forceinline__ float2 upk2(ull v){
    float2 f; asm("mov.b64 {%0, %1}, %2;" : "=f"(f.x), "=f"(f.y) : "l"(v)); return f;
}
__device__ __forceinline__ void ffma2(ull &c, ull a, ull b){
    asm("fma.rn.f32x2 %0, %1, %2, %0;" : "+l"(c) : "l"(a), "l"(b));
}
__device__ __forceinline__ float ex2f(float x){
    float r; asm("ex2.approx.ftz.f32 %0, %1;" : "=f"(r) : "f"(x)); return r;
}
__device__ __forceinline__ float lg2f(float x){
    float r; asm("lg2.approx.ftz.f32 %0, %1;" : "=f"(r) : "f"(x)); return r;
}
#define LOG2E  1.4426950408889634f
#define RLOG2E 0.6931471805599453f
__device__ __forceinline__ float silu_f(float x){ return x / (1.f + ex2f(-LOG2E*x)); }
__device__ __forceinline__ float softplus_f(float x){
    float r = lg2f(1.f + ex2f(x*LOG2E)) * RLOG2E;
    return x > 20.f ? x : r;
}
__device__ __forceinline__ uint32_t smem_u32(const void* p){
    uint32_t a; asm("{ .reg .u64 t; cvta.to.shared.u64 t, %1; cvt.u32.u64 %0, t; }"
                    : "=r"(a) : "l"(p));
    return a;
}

// ldmatrix x4 (non-trans)
#define LDSM4(r0,r1,r2,r3,addr) \
    asm volatile("ldmatrix.sync.aligned.m8n8.x4.shared.b16 {%0,%1,%2,%3}, [%4];" \
        : "=r"(r0), "=r"(r1), "=r"(r2), "=r"(r3) : "r"(addr))

// mma m16n8k16 bf16 -> fp32
#define MMA16816(c, a, b) \
    asm volatile("mma.sync.aligned.m16n8k16.row.col.f32.bf16.bf16.f32 " \
        "{%0,%1,%2,%3}, {%4,%5,%6,%7}, {%8,%9}, {%0,%1,%2,%3};" \
        : "+f"((c)[0]), "+f"((c)[1]), "+f"((c)[2]), "+f"((c)[3]) \
        : "r"((a)[0]), "r"((a)[1]), "r"((a)[2]), "r"((a)[3]), "r"((b)[0]), "r"((b)[1]))

// row remap helpers (prep / final fused)
__device__ __forceinline__ const float* arow(const float* Abase, int asel, int rr, int K,
                                             const float* xp){
    if (asel == 3){
        int sio = rr>>10, b = sio&1, c = sio>>1, l = rr&(L-1);
        return xp + ((size_t)(b*L + (c ? (L-1-l) : l)))*DM;
    }
    return Abase + (size_t)rr*K;
}
__device__ __forceinline__ float* crow(float* Cbase, int csel, int rr, int N, float* outp){
    if (csel == 3){
        int sio = rr>>10, b = sio&1, c = sio>>1, l = rr&(L-1);
        return outp + ((size_t)(b*L + (c ? (L-1-l) : l)))*(2*DM) + c*DM;
    }
    return Cbase + (size_t)rr*N;
}

// ---------------- A2 table ----------------
__global__ void a2_kernel(const float* __restrict__ A_log){
    int idx = blockIdx.x*blockDim.x + threadIdx.x;
    g_A2[idx] = -expf(A_log[idx]) * LOG2E;
}

// ---------------- bf16 hi/lo conversions ----------------
__global__ void cvtW(const float* __restrict__ W, __nv_bfloat16* __restrict__ wh,
                     __nv_bfloat16* __restrict__ wl){
    int idx = blockIdx.x*blockDim.x + threadIdx.x;
    float v = W[idx];
    __nv_bfloat16 h = __float2bfloat16(v);
    wh[idx] = h;
    wl[idx] = __float2bfloat16(v - __bfloat162float(h));
}
__global__ void cvtA(int asel, int kshift, const float* __restrict__ xin){
    int idx = blockIdx.x*blockDim.x + threadIdx.x;
    int K = 1 << kshift;
    int r = idx >> kshift, k = idx & (K-1);
    const float* ap = arow((asel==1)? g_a1 : g_y, asel, r, K, xin);
    float v = ap[k];
    __nv_bfloat16 h = __float2bfloat16(v);
    g_Ah[idx] = h;
    g_Al[idx] = __float2bfloat16(v - __bfloat162float(h));
}

// ============== gemm3: mma.sync bf16x3 split-precision GEMM ==============
// C[r,n] = sum_k A[r,k]*W[n,k]; A [M,KTOT] row-major (g_Ah/g_Al),
// W [N,KTOT] row-major (= B col-major for mma row.col).
// Block: BM x BN tile, 256 thr = 8 warps laid out WRM x WRN.
// Warp tile: (BM/WRM) x (BN/WRN); MT=m16 tiles, NT=n8 tiles per warp.
template<int BM, int BN, int WRM, int WRN, int KTOT>
__global__ __launch_bounds__(256) void gemm3(
    const __nv_bfloat16* __restrict__ Wh, const __nv_bfloat16* __restrict__ Wl,
    int csel, int N, int lay, float* __restrict__ outp)
{
    constexpr int KC  = 32;
    constexpr int AST = KC + 8;            // smem row stride in bf16 (80B)
    constexpr int WTM = BM/WRM;            // warp tile m
    constexpr int WTN = BN/WRN;            // warp tile n
    constexpr int MT  = WTM/16;
    constexpr int NT  = WTN/8;
    constexpr int NCH = KTOT/KC;

    __shared__ __nv_bfloat16 sAh[BM*AST], sAl[BM*AST];
    __shared__ __nv_bfloat16 sBh[BN*AST], sBl[BN*AST];

    int tid = threadIdx.x, wid = tid>>5, lane = tid&31;
    int wm = wid % WRM, wn = wid / WRM;
    int r0 = blockIdx.y*BM, n0 = blockIdx.x*BN;
    int si = r0>>10, wl_ = lay + 2*(si>>1);

    float* Cout = (csel==1) ? g_a1 : g_xz;   // csel==3 via crow
    const __nv_bfloat16* Whb = Wh + (size_t)wl_*N*KTOT + (size_t)n0*KTOT;
    const __nv_bfloat16* Wlb = Wl + (size_t)wl_*N*KTOT + (size_t)n0*KTOT;
    const __nv_bfloat16* Ahb = g_Ah + (size_t)r0*KTOT;
    const __nv_bfloat16* Alb = g_Al + (size_t)r0*KTOT;

    float acc[MT][NT][4];
    #pragma unroll
    for (int i=0;i<MT;i++)
        #pragma unroll
        for (int j=0;j<NT;j++){
            acc[i][j][0]=0.f; acc[i][j][1]=0.f; acc[i][j][2]=0.f; acc[i][j][3]=0.f;
        }

    uint32_t aH = smem_u32(sAh), aL = smem_u32(sAl);
    uint32_t bH = smem_u32(sBh), bL = smem_u32(sBl);

    // ldmatrix lane address components (bytes)
    int arow_l = wm*WTM + (lane&15);
    uint32_t aoff0 = (uint32_t)arow_l*AST*2 + (uint32_t)(lane>>4)*16;
    int nsub = wn*WTN + (lane&7) + ((lane>>4)&1)*8;
    uint32_t boff0 = (uint32_t)nsub*AST*2 + (uint32_t)((lane>>3)&1)*16;

    for (int kc=0; kc<NCH; kc++){
        // A tile: BM rows x 32 bf16 (4 x uint4 per row)
        #pragma unroll
        for (int i=tid; i<BM*4; i+=256){
            int row = i>>2, c = i&3;
            const uint4* ph = (const uint4*)(Ahb + (size_t)row*KTOT + kc*KC);
            const uint4* pl = (const uint4*)(Alb + (size_t)row*KTOT + kc*KC);
            *(uint4*)&sAh[row*AST + c*8] = ph[c];
            *(uint4*)&sAl[row*AST + c*8] = pl[c];
        }
        // B tile: BN rows x 32 bf16
        #pragma unroll
        for (int i=tid; i<BN*4; i+=256){
            int row = i>>2, c = i&3;
            const uint4* ph = (const uint4*)(Whb + (size_t)row*KTOT + kc*KC);
            const uint4* pl = (const uint4*)(Wlb + (size_t)row*KTOT + kc*KC);
            *(uint4*)&sBh[row*AST + c*8] = ph[c];
            *(uint4*)&sBl[row*AST + c*8] = pl[c];
        }
        __syncthreads();
        #pragma unroll
        for (int ks=0; ks<2; ks++){
            uint32_t akoff = aoff0 + ks*32;   // ks*16 bf16 = 32B
            uint32_t bkoff = boff0 + ks*32;
            uint32_t ah[MT][4], al[MT][4], bh[NT][2], bl[NT][2];
            #pragma unroll
            for (int tm=0; tm<MT; tm++){
                uint32_t ad = akoff + (uint32_t)(tm*16*AST*2);
                LDSM4(ah[tm][0],ah[tm][1],ah[tm][2],ah[tm][3], aH + ad);
                LDSM4(al[tm][0],al[tm][1],al[tm][2],al[tm][3], aL + ad);
            }
            #pragma unroll
            for (int p=0; p<NT/2; p++){
                uint32_t bd = bkoff + (uint32_t)(p*16*AST*2);
                uint32_t r0_,r1_,r2_,r3_;
                LDSM4(r0_,r1_,r2_,r3_, bH + bd);
                bh[2*p][0]=r0_; bh[2*p][1]=r1_; bh[2*p+1][0]=r2_; bh[2*p+1][1]=r3_;
                LDSM4(r0_,r1_,r2_,r3_, bL + bd);
                bl[2*p][0]=r0_; bl[2*p][1]=r1_; bl[2*p+1][0]=r2_; bl[2*p+1][1]=r3_;
            }
            #pragma unroll
            for (int tm=0; tm<MT; tm++)
                #pragma unroll
                for (int tn=0; tn<NT; tn++){
                    MMA16816(acc[tm][tn], ah[tm], bh[tn]);
                    MMA16816(acc[tm][tn], ah[tm], bl[tn]);
                    MMA16816(acc[tm][tn], al[tm], bh[tn]);
                }
        }
        __syncthreads();
    }
    // epilogue: c0,c1 -> (row, col..col+1); c2,c3 -> (row+8, ...)
    int mbase = r0 + wm*WTM;
    int nbase = n0 + wn*WTN;
    #pragma unroll
    for (int tm=0; tm<MT; tm++){
        int row = mbase + tm*16 + (lane>>2);
        float* p0r = crow(Cout, csel, row,     N, outp);
        float* p1r = crow(Cout, csel, row + 8, N, outp);
        #pragma unroll
        for (int tn=0; tn<NT; tn++){
            int col = nbase + tn*8 + (lane&3)*2;
            *(float2*)(p0r + col) = make_float2(acc[tm][tn][0], acc[tm][tn][1]);
            *(float2*)(p1r + col) = make_float2(acc[tm][tn][2], acc[tm][tn][3]);
        }
    }
}

// ============== xproj3: fused conv+silu + dbl = xc @ Wx^T (k-split x2) ==============
__global__ __launch_bounds__(256) void xproj3(const float* __restrict__ Wx,
                                              const float* __restrict__ cw,
                                              const float* __restrict__ cb, int lay){
    __shared__ float sA[32*130];
    __shared__ float sW[48*130];

    int tid = threadIdx.x;
    int tx  = tid & 15, ty = tid >> 4;
    int r0  = blockIdx.x*32;
    int kh  = blockIdx.y;            // k half: [kh*256, kh*256+256)
    int si  = r0 >> 10;
    int wl  = lay + 2*(si>>1);
    const float* Wb  = Wx + (size_t)wl*48*DI;
    const float* cwb = cw + (size_t)wl*DI*4;
    const float* cbb = cb + (size_t)wl*DI;

    ull acc[2][3];
    #pragma unroll
    for (int i=0;i<2;i++){ acc[i][0]=0ull; acc[i][1]=0ull; acc[i][2]=0ull; }

    for (int kc=0; kc<2; kc++){
        int k0 = kh*256 + kc*128;
        #pragma unroll
        for (int it=0; it<4; it++){
            int i = tid + it*256;            // 0..1023
            int r = i>>5, q = i&31;
            int rr = r0 + r, l = rr & (L-1);
            int d0 = k0 + q*4;
            const float* xp = g_xz + (size_t)rr*(2*DI) + d0;
            float4 z4 = make_float4(0.f,0.f,0.f,0.f);
            float4 v0 = (l>=3) ? *(const float4*)(xp - 3*(2*DI)) : z4;
            float4 v1 = (l>=2) ? *(const float4*)(xp - 2*(2*DI)) : z4;
            float4 v2 = (l>=1) ? *(const float4*)(xp - 1*(2*DI)) : z4;
            float4 v3 = *(const float4*)(xp);
            float4 w0 = *(const float4*)(cwb + (size_t)d0*4);
            float4 w1 = *(const float4*)(cwb + (size_t)d0*4 + 4);
            float4 w2 = *(const float4*)(cwb + (size_t)d0*4 + 8);
            float4 w3 = *(const float4*)(cwb + (size_t)d0*4 + 12);
            float4 bb = *(const float4*)(cbb + d0);
            float s0 = bb.x + v0.x*w0.x + v1.x*w0.y + v2.x*w0.z + v3.x*w0.w;
            float s1 = bb.y + v0.y*w1.x + v1.y*w1.y + v2.y*w1.z + v3.y*w1.w;
            float s2 = bb.z + v0.z*w2.x + v1.z*w2.y + v2.z*w2.z + v3.z*w2.w;
            float s3 = bb.w + v0.w*w3.x + v1.w*w3.y + v2.w*w3.z + v3.w*w3.w;
            s0 = silu_f(s0); s1 = silu_f(s1); s2 = silu_f(s2); s3 = silu_f(s3);
            float* ap = &sA[r*130 + q*4];
            ap[0]=s0; ap[1]=s1; ap[2]=s2; ap[3]=s3;
            *(float4*)(g_xc + (size_t)rr*DI + d0) = make_float4(s0,s1,s2,s3);
        }
        #pragma unroll
        for (int it=0; it<6; it++){
            int i = tid + it*256;            // 0..1535
            int j = i>>5, q = i&31;
            float4 v = *(const float4*)(Wb + (size_t)j*DI + k0 + q*4);
            float* wp = &sW[j*130 + q*4];
            wp[0]=v.x; wp[1]=v.y; wp[2]=v.z; wp[3]=v.w;
        }
        __syncthreads();
        const ull* a0p = (const ull*)&sA[(ty*2  )*130];
        const ull* a1p = (const ull*)&sA[(ty*2+1)*130];
        const ull* w0p = (const ull*)&sW[(tx    )*130];
        const ull* w1p = (const ull*)&sW[(tx+16 )*130];
        const ull* w2p = (const ull*)&sW[(tx+32 )*130];
        #pragma unroll 8
        for (int k2=0;k2<64;k2++){
            ull a0=a0p[k2], a1=a1p[k2];
            ull b0=w0p[k2], b1=w1p[k2], b2=w2p[k2];
            ffma2(acc[0][0],a0,b0); ffma2(acc[0][1],a0,b1); ffma2(acc[0][2],a0,b2);
            ffma2(acc[1][0],a1,b0); ffma2(acc[1][1],a1,b1); ffma2(acc[1][2],a1,b2);
        }
        __syncthreads();
    }
    #pragma unroll
    for (int i=0;i<2;i++){
        int rr = r0 + ty*2 + i;
        float* dp = g_dblp[kh] + (size_t)rr*48;
        float2 v0=upk2(acc[i][0]), v1=upk2(acc[i][1]), v2=upk2(acc[i][2]);
        dp[tx]    = v0.x+v0.y;
        dp[tx+16] = v1.x+v1.y;
        dp[tx+32] = v2.x+v2.y;
    }
}

// ---------------- dt2: tiled dt = softplus(dtr @ Wdt^T + b) ----------------
__global__ __launch_bounds__(256) void dt2(const float* __restrict__ Wdt,
                                           const float* __restrict__ bdt, int lay){
    __shared__ float sd[64][17];
    __shared__ float sw[16][128];
    __shared__ float sb[128];

    int tid = threadIdx.x;
    int d0  = blockIdx.x*128;
    int r0  = blockIdx.y*64;
    int si  = r0 >> 10;
    int wl  = lay + 2*(si>>1);

    {
        int r = tid>>2, q4 = (tid&3)*4;
        const float4 a = *(const float4*)(g_dblp[0] + (size_t)(r0+r)*48 + q4);
        const float4 b = *(const float4*)(g_dblp[1] + (size_t)(r0+r)*48 + q4);
        sd[r][q4+0]=a.x+b.x; sd[r][q4+1]=a.y+b.y; sd[r][q4+2]=a.z+b.z; sd[r][q4+3]=a.w+b.w;
    }
    #pragma unroll
    for (int it=0; it<2; it++){
        int i = tid + it*256;
        int j = i>>2, q4 = (i&3)*4;
        float4 v = *(const float4*)(Wdt + (size_t)(wl*DI + d0 + j)*RK + q4);
        sw[q4+0][j]=v.x; sw[q4+1][j]=v.y; sw[q4+2][j]=v.z; sw[q4+3][j]=v.w;
    }
    if (tid < 128) sb[tid] = bdt[wl*DI + d0 + tid];
    __syncthreads();

    int td = tid & 127, half = tid >> 7;
    float w[16];
    #pragma unroll
    for (int q=0;q<16;q++) w[q] = sw[q][td];
    float bias = sb[td];
    #pragma unroll 4
    for (int rr=0; rr<32; rr++){
        int r = half*32 + rr;
        float acc = bias;
        #pragma unroll
        for (int q=0;q<16;q++) acc = fmaf(sd[r][q], w[q], acc);
        g_dt[(size_t)(r0+r)*DI + d0 + td] = softplus_f(acc);
    }
}

// ---------------- scan phase 1 (256 thr, s-split x2) ----------------
__global__ __launch_bounds__(256) void scan_phase1(int lay){
    int tid = threadIdx.x;
    int dl  = tid & 127;
    int sh  = tid >> 7;
    int d0b = blockIdx.x*128;
    int d   = d0b + dl;
    int ch  = blockIdx.y;
    int si  = blockIdx.z;
    int wl  = lay + 2*(si>>1);
    __shared__ float sdt[CLEN][128];
    __shared__ float sxc[CLEN][128];
    __shared__ float sB[CLEN][DS];
    int rbase = si*L + ch*CLEN;
    #pragma unroll
    for (int it=0; it<CLEN/8; it++){
        int i  = tid + it*256;
        int ll = i >> 5, dd = (i & 31)*4;
        *(float4*)&sdt[ll][dd] = *(const float4*)(g_dt + (size_t)(rbase+ll)*DI + d0b + dd);
        *(float4*)&sxc[ll][dd] = *(const float4*)(g_xc + (size_t)(rbase+ll)*DI + d0b + dd);
    }
    #pragma unroll
    for (int i=tid; i<CLEN*DS; i+=256){
        int ll = i>>4, s = i&15;
        size_t off = (size_t)(rbase+ll)*48 + 16 + s;
        sB[ll][s] = g_dblp[0][off] + g_dblp[1][off];
    }
    __syncthreads();
    float A2[8], h[8];
    {
        const float4* ap = (const float4*)(g_A2 + (size_t)(wl*DI+d)*DS + sh*8);
        float4 v0 = ap[0], v1 = ap[1];
        A2[0]=v0.x; A2[1]=v0.y; A2[2]=v0.z; A2[3]=v0.w;
        A2[4]=v1.x; A2[5]=v1.y; A2[6]=v1.z; A2[7]=v1.w;
    }
    #pragma unroll
    for (int s=0;s<8;s++) h[s]=0.f;
    float sdtacc = 0.f;
    #pragma unroll 4
    for (int ll=0; ll<CLEN; ll++){
        float dtc = sdt[ll][dl];
        float xcv = sxc[ll][dl];
        float dtx = dtc*xcv;
        sdtacc += dtc;
        #pragma unroll
        for (int s=0;s<8;s++){
            float dA = ex2f(dtc*A2[s]);
            h[s] = fmaf(dA, h[s], dtx*sB[ll][sh*8+s]);
        }
    }
    size_t ob = ((size_t)(si*DI + d)*CH + ch)*DS + sh*8;
    float P[8];
    #pragma unroll
    for (int s=0;s<8;s++) P[s] = ex2f(sdtacc*A2[s]);
    *(float4*)(g_H+ob)   = make_float4(h[0],h[1],h[2],h[3]);
    *(float4*)(g_H+ob+4) = make_float4(h[4],h[5],h[6],h[7]);
    *(float4*)(g_P+ob)   = make_float4(P[0],P[1],P[2],P[3]);
    *(float4*)(g_P+ob+4) = make_float4(P[4],P[5],P[6],P[7]);
}

// ---------------- scan combine ----------------
__global__ void scan_comb(){
    int idx = blockIdx.x*blockDim.x + threadIdx.x;
    int s = idx & 15;
    int t = idx >> 4;
    size_t base = (size_t)t*CH*DS + s;
    float run = 0.f;
    #pragma unroll 8
    for (int c=0;c<CH;c++){
        size_t p = base + (size_t)c*DS;
        float he = g_H[p], pe = g_P[p];
        g_H[p] = run;
        run = fmaf(pe, run, he);
    }
}

// ---------------- scan phase 2 (256 thr, s-split in-warp) ----------------
__global__ __launch_bounds__(256) void scan_phase2(const float* __restrict__ Dp, int lay){
    int tid  = threadIdx.x;
    int w    = tid >> 5, lane = tid & 31;
    int sh   = lane >> 4;
    int dl   = w*16 + (lane & 15);
    int d0b  = blockIdx.x*128;
    int d    = d0b + dl;
    int ch   = blockIdx.y;
    int si   = blockIdx.z;
    int wl   = lay + 2*(si>>1);
    __shared__ float sdt[CLEN][128];
    __shared__ float sxc[CLEN][128];
    __shared__ float sB[CLEN][DS];
    __shared__ float sC[CLEN][DS];
    int rbase = si*L + ch*CLEN;
    #pragma unroll
    for (int it=0; it<CLEN/8; it++){
        int i  = tid + it*256;
        int ll = i >> 5, dd = (i & 31)*4;
        *(float4*)&sdt[ll][dd] = *(const float4*)(g_dt + (size_t)(rbase+ll)*DI + d0b + dd);
        *(float4*)&sxc[ll][dd] = *(const float4*)(g_xc + (size_t)(rbase+ll)*DI + d0b + dd);
    }
    #pragma unroll
    for (int i=tid; i<CLEN*DS; i+=256){
        int ll = i>>4, s = i&15;
        size_t off = (size_t)(rbase+ll)*48 + 16 + s;
        sB[ll][s] = g_dblp[0][off]    + g_dblp[1][off];
        sC[ll][s] = g_dblp[0][off+16] + g_dblp[1][off+16];
    }
    __syncthreads();
    float A2[8], h[8];
    size_t ib = ((size_t)(si*DI + d)*CH + ch)*DS + sh*8;
    {
        const float4* ap = (const float4*)(g_A2 + (size_t)(wl*DI+d)*DS + sh*8);
        float4 v0 = ap[0], v1 = ap[1];
        A2[0]=v0.x; A2[1]=v0.y; A2[2]=v0.z; A2[3]=v0.w;
        A2[4]=v1.x; A2[5]=v1.y; A2[6]=v1.z; A2[7]=v1.w;
        float4 h0 = *(const float4*)(g_H+ib);
        float4 h1 = *(const float4*)(g_H+ib+4);
        h[0]=h0.x; h[1]=h0.y; h[2]=h0.z; h[3]=h0.w;
        h[4]=h1.x; h[5]=h1.y; h[6]=h1.z; h[7]=h1.w;
    }
    float Dd = Dp[wl*DI + d];
    #pragma unroll 4
    for (int ll=0; ll<CLEN; ll++){
        int r = rbase + ll;
        float dtc = sdt[ll][dl];
        float xcv = sxc[ll][dl];
        float z   = g_xz[(size_t)r*(2*DI) + DI + d];
        float dtx = dtc*xcv;
        float y0=0.f, y1=0.f;
        #pragma unroll
        for (int s=0;s<8;s++){
            float dA = ex2f(dtc*A2[s]);
            h[s] = fmaf(dA, h[s], dtx*sB[ll][sh*8+s]);
            if (s & 1) y1 = fmaf(h[s], sC[ll][sh*8+s], y1);
            else       y0 = fmaf(h[s], sC[ll][sh*8+s], y0);
        }
        float yp = y0 + y1;
        float y  = yp + __shfl_xor_sync(0xffffffffu, yp, 16);
        if (sh == 0){
            y = fmaf(xcv, Dd, y);
            y *= silu_f(z);
            g_y[(size_t)r*DI + d] = y;
        }
    }
}

// ---------------- launch ----------------
extern "C" void kernel_launch(void* const* d_in, const int* in_sizes, int n_in,
                              void* d_out, int out_size)
{
    (void)in_sizes; (void)n_in; (void)out_size;
    const float* x        = (const float*)d_in[0];
    const float* in_proj  = (const float*)d_in[1];
    const float* conv_w   = (const float*)d_in[2];
    const float* conv_b   = (const float*)d_in[3];
    const float* x_proj   = (const float*)d_in[4];
    const float* dt_proj  = (const float*)d_in[5];
    const float* dt_bias  = (const float*)d_in[6];
    const float* A_log    = (const float*)d_in[7];
    const float* Dp       = (const float*)d_in[8];
    const float* out_proj = (const float*)d_in[9];
    float* out = (float*)d_out;

    a2_kernel<<<4*DI*DS/256, 256>>>(A_log);
    cvtW<<<4*1024*256/256, 256>>>(in_proj,  g_Wih, g_Wil);
    cvtW<<<4*256*512/256, 256>>>(out_proj, g_Woh, g_Wol);

    for (int lay = 0; lay < 2; lay++){
        int ain  = lay ? 1 : 3;        // layer0 reads x with prep-remap
        int cout = lay ? 3 : 1;        // layer1 writes out with final-remap

        // xz = act @ in_proj^T   (N=1024, K=256) via mma.sync bf16x3
        cvtA<<<ROWS*256/256, 256>>>(ain, 8, x);
        gemm3<128,64,4,2,256><<<dim3(1024/64, ROWS/128), 256>>>(
            g_Wih, g_Wil, 2, 1024, lay, nullptr);
        xproj3<<<dim3(ROWS/32, 2), 256>>>(x_proj, conv_w, conv_b, lay);
        dt2<<<dim3(DI/128, ROWS/64), 256>>>(dt_proj, dt_bias, lay);
        scan_phase1<<<dim3(DI/128, CH, NSEQ), 256>>>(lay);
        scan_comb<<<NSEQ*DI*DS/256, 256>>>();
        scan_phase2<<<dim3(DI/128, CH, NSEQ), 256>>>(Dp, lay);
        // act_out = y @ out_proj^T  (N=256, K=512) via mma.sync bf16x3
        cvtA<<<ROWS*512/256, 256>>>(2, 9, nullptr);
        gemm3<64,64,2,4,512><<<dim3(256/64, ROWS/64), 256>>>(
            g_Woh, g_Wol, cout, 256, lay, out);
    }
}

// round 16
// speedup vs baseline: 3.4128x; 3.4128x over previous
#include <cuda_runtime.h>
#include <cstdint>
#include <cstddef>

#define L     1024
#define DM    256
#define DI    512
#define DS    16
#define RK    16
#define NSEQ  4
#define ROWS  (NSEQ*L)      // 4096
#define CH    32
#define CLEN  (L/CH)        // 32

typedef unsigned long long ull;

// ---------------- device scratch ----------------
__device__ float g_a1[ROWS*DM];          // inter-layer activation
__device__ float g_xz[ROWS*2*DI];        // in_proj output (xc | z)
__device__ float g_xc[ROWS*DI];          // conv+silu output
__device__ float g_dblp[2][ROWS*48];     // x_proj partial outputs (k-split)
__device__ float g_dt[ROWS*DI];          // softplus dt
__device__ float g_y[ROWS*DI];           // gated scan output
__device__ float g_P[NSEQ*DI*CH*DS];     // per-chunk decay
__device__ float g_H[NSEQ*DI*CH*DS];     // per-chunk end state -> init state
__device__ float g_A2[4*DI*DS];          // precomputed -exp(A_log)*log2e

// ---------------- helpers ----------------
__device__ __forceinline__ ull pk2(float x, float y){
    ull r; asm("mov.b64 %0, {%1, %2};" : "=l"(r) : "f"(x), "f"(y)); return r;
}
__device__ __forceinline__ float2 upk2(ull v){
    float2 f; asm("mov.b64 {%0, %1}, %2;" : "=f"(f.x), "=f"(f.y) : "l"(v)); return f;
}
__device__ __forceinline__ void ffma2(ull &c, ull a, ull b){
    asm("fma.rn.f32x2 %0, %1, %2, %0;" : "+l"(c) : "l"(a), "l"(b));
}
__device__ __forceinline__ float ex2f(float x){
    float r; asm("ex2.approx.ftz.f32 %0, %1;" : "=f"(r) : "f"(x)); return r;
}
__device__ __forceinline__ float lg2f(float x){
    float r; asm("lg2.approx.ftz.f32 %0, %1;" : "=f"(r) : "f"(x)); return r;
}
#define LOG2E  1.4426950408889634f
#define RLOG2E 0.6931471805599453f
__device__ __forceinline__ float silu_f(float x){ return x / (1.f + ex2f(-LOG2E*x)); }
__device__ __forceinline__ float softplus_f(float x){
    float r = lg2f(1.f + ex2f(x*LOG2E)) * RLOG2E;
    return x > 20.f ? x : r;
}

// row remap helpers (prep / final fused into GEMM)
__device__ __forceinline__ const float* arow(const float* Abase, int asel, int rr, int K,
                                             const float* xp){
    if (asel == 3){
        int sio = rr>>10, b = sio&1, c = sio>>1, l = rr&(L-1);
        return xp + ((size_t)(b*L + (c ? (L-1-l) : l)))*DM;
    }
    return Abase + (size_t)rr*K;
}
__device__ __forceinline__ float* crow(float* Cbase, int csel, int rr, int N, float* outp){
    if (csel == 3){
        int sio = rr>>10, b = sio&1, c = sio>>1, l = rr&(L-1);
        return outp + ((size_t)(b*L + (c ? (L-1-l) : l)))*(2*DM) + c*DM;
    }
    return Cbase + (size_t)rr*N;
}

// ---------------- A2 table: -exp(A_log) * log2e ----------------
__global__ void a2_kernel(const float* __restrict__ A_log){
    int idx = blockIdx.x*blockDim.x + threadIdx.x;   // 4*DI*DS
    g_A2[idx] = -expf(A_log[idx]) * LOG2E;
}

// ============== gemm2: C[r,n] = sum_k A[r,k]*W[n,k] ==============
// BM x BN block tile, 256 threads (16x16). Row-pair f32x2 accumulators.
// Register double-buffering: next k-tile LDGs issued before compute, latency
// hidden behind the FFMA2 stream.
// asel: 1=g_a1 2=g_y 3=x(remap) ; csel: 1=g_a1 2=g_xz 3=out(remap)
template<int BM, int BN>
__global__ __launch_bounds__(256) void gemm2(int asel, const float* __restrict__ Wall,
                                             int csel, int N, int K, int lay,
                                             const float* __restrict__ xin,
                                             float* __restrict__ outp)
{
    const float* A    = (asel==1) ? g_a1 : g_y;   // asel==3 handled in arow
    float*       Cout = (csel==1) ? g_a1 : g_xz;

    constexpr int RT = BM/16;             // rows per thread
    constexpr int NP = RT/2;              // row pairs per thread
    constexpr int CN = BN/16;             // cols per thread
    constexpr int NA = BM/64;             // A float4 loads per thread
    constexpr int NB = BN/64;             // B float4 loads per thread

    __shared__ float As[16*(BM+4)];
    __shared__ float Bs[16*(BN+4)];

    int tid = threadIdx.x;
    int tx  = tid & 15, ty = tid >> 4;
    int r0  = blockIdx.y*BM;
    int n0  = blockIdx.x*BN;
    int si  = r0 >> 10;
    int wl  = lay + 2*(si>>1);
    const float* W = Wall + (size_t)wl*N*K;

    ull acc[NP][CN];
    #pragma unroll
    for (int p=0;p<NP;p++)
        #pragma unroll
        for (int c=0;c<CN;c++) acc[p][c]=0ull;

    int ra = (tid>>2), ka = (tid&3)*4;

    // prologue: load k-tile 0 into registers
    float4 pa[NA], pb[NB];
    #pragma unroll
    for (int it=0; it<NA; it++)
        pa[it] = *(const float4*)(arow(A, asel, r0+ra+it*64, K, xin) + ka);
    #pragma unroll
    for (int it=0; it<NB; it++)
        pb[it] = *(const float4*)(W + (size_t)(n0+ra+it*64)*K + ka);

    for (int k0=0; k0<K; k0+=16){
        // stage current tile into smem
        #pragma unroll
        for (int it=0; it<NA; it++){
            int r = ra + it*64;
            As[(ka+0)*(BM+4)+r]=pa[it].x; As[(ka+1)*(BM+4)+r]=pa[it].y;
            As[(ka+2)*(BM+4)+r]=pa[it].z; As[(ka+3)*(BM+4)+r]=pa[it].w;
        }
        #pragma unroll
        for (int it=0; it<NB; it++){
            int n = ra + it*64;
            Bs[(ka+0)*(BN+4)+n]=pb[it].x; Bs[(ka+1)*(BN+4)+n]=pb[it].y;
            Bs[(ka+2)*(BN+4)+n]=pb[it].z; Bs[(ka+3)*(BN+4)+n]=pb[it].w;
        }
        __syncthreads();
        // prefetch next k-tile (LDGs fly during compute)
        if (k0 + 16 < K){
            #pragma unroll
            for (int it=0; it<NA; it++)
                pa[it] = *(const float4*)(arow(A, asel, r0+ra+it*64, K, xin) + k0+16 + ka);
            #pragma unroll
            for (int it=0; it<NB; it++)
                pb[it] = *(const float4*)(W + (size_t)(n0+ra+it*64)*K + k0+16 + ka);
        }
        #pragma unroll
        for (int k=0;k<16;k++){
            const ull* ap = (const ull*)&As[k*(BM+4) + ty*RT];
            ull av[NP];
            #pragma unroll
            for (int p=0;p<NP;p++) av[p]=ap[p];
            float bv[CN];
            #pragma unroll
            for (int v4=0; v4<CN/4; v4++){
                float4 b4 = *(const float4*)&Bs[k*(BN+4) + tx*CN + v4*4];
                bv[v4*4+0]=b4.x; bv[v4*4+1]=b4.y; bv[v4*4+2]=b4.z; bv[v4*4+3]=b4.w;
            }
            #pragma unroll
            for (int c=0;c<CN;c++){
                ull bb = pk2(bv[c], bv[c]);
                #pragma unroll
                for (int p=0;p<NP;p++) ffma2(acc[p][c], av[p], bb);
            }
        }
        __syncthreads();
    }
    #pragma unroll
    for (int p=0;p<NP;p++){
        float lo[CN], hi[CN];
        #pragma unroll
        for (int c=0;c<CN;c++){ float2 v = upk2(acc[p][c]); lo[c]=v.x; hi[c]=v.y; }
        float* c0 = crow(Cout, csel, r0 + ty*RT + 2*p,     N, outp) + n0 + tx*CN;
        float* c1 = crow(Cout, csel, r0 + ty*RT + 2*p + 1, N, outp) + n0 + tx*CN;
        #pragma unroll
        for (int v4=0; v4<CN/4; v4++){
            ((float4*)c0)[v4] = make_float4(lo[4*v4],lo[4*v4+1],lo[4*v4+2],lo[4*v4+3]);
            ((float4*)c1)[v4] = make_float4(hi[4*v4],hi[4*v4+1],hi[4*v4+2],hi[4*v4+3]);
        }
    }
}

// ============== xproj3: fused conv+silu + dbl = xc @ Wx^T (k-split x2) ==============
__global__ __launch_bounds__(256) void xproj3(const float* __restrict__ Wx,
                                              const float* __restrict__ cw,
                                              const float* __restrict__ cb, int lay){
    __shared__ float sA[32*130];
    __shared__ float sW[48*130];

    int tid = threadIdx.x;
    int tx  = tid & 15, ty = tid >> 4;
    int r0  = blockIdx.x*32;
    int kh  = blockIdx.y;            // k half: [kh*256, kh*256+256)
    int si  = r0 >> 10;
    int wl  = lay + 2*(si>>1);
    const float* Wb  = Wx + (size_t)wl*48*DI;
    const float* cwb = cw + (size_t)wl*DI*4;
    const float* cbb = cb + (size_t)wl*DI;

    ull acc[2][3];
    #pragma unroll
    for (int i=0;i<2;i++){ acc[i][0]=0ull; acc[i][1]=0ull; acc[i][2]=0ull; }

    for (int kc=0; kc<2; kc++){
        int k0 = kh*256 + kc*128;
        #pragma unroll
        for (int it=0; it<4; it++){
            int i = tid + it*256;            // 0..1023
            int r = i>>5, q = i&31;
            int rr = r0 + r, l = rr & (L-1);
            int d0 = k0 + q*4;
            const float* xp = g_xz + (size_t)rr*(2*DI) + d0;
            float4 z4 = make_float4(0.f,0.f,0.f,0.f);
            float4 v0 = (l>=3) ? *(const float4*)(xp - 3*(2*DI)) : z4;
            float4 v1 = (l>=2) ? *(const float4*)(xp - 2*(2*DI)) : z4;
            float4 v2 = (l>=1) ? *(const float4*)(xp - 1*(2*DI)) : z4;
            float4 v3 = *(const float4*)(xp);
            float4 w0 = *(const float4*)(cwb + (size_t)d0*4);
            float4 w1 = *(const float4*)(cwb + (size_t)d0*4 + 4);
            float4 w2 = *(const float4*)(cwb + (size_t)d0*4 + 8);
            float4 w3 = *(const float4*)(cwb + (size_t)d0*4 + 12);
            float4 bb = *(const float4*)(cbb + d0);
            float s0 = bb.x + v0.x*w0.x + v1.x*w0.y + v2.x*w0.z + v3.x*w0.w;
            float s1 = bb.y + v0.y*w1.x + v1.y*w1.y + v2.y*w1.z + v3.y*w1.w;
            float s2 = bb.z + v0.z*w2.x + v1.z*w2.y + v2.z*w2.z + v3.z*w2.w;
            float s3 = bb.w + v0.w*w3.x + v1.w*w3.y + v2.w*w3.z + v3.w*w3.w;
            s0 = silu_f(s0); s1 = silu_f(s1); s2 = silu_f(s2); s3 = silu_f(s3);
            float* ap = &sA[r*130 + q*4];
            ap[0]=s0; ap[1]=s1; ap[2]=s2; ap[3]=s3;
            *(float4*)(g_xc + (size_t)rr*DI + d0) = make_float4(s0,s1,s2,s3);
        }
        #pragma unroll
        for (int it=0; it<6; it++){
            int i = tid + it*256;            // 0..1535
            int j = i>>5, q = i&31;
            float4 v = *(const float4*)(Wb + (size_t)j*DI + k0 + q*4);
            float* wp = &sW[j*130 + q*4];
            wp[0]=v.x; wp[1]=v.y; wp[2]=v.z; wp[3]=v.w;
        }
        __syncthreads();
        const ull* a0p = (const ull*)&sA[(ty*2  )*130];
        const ull* a1p = (const ull*)&sA[(ty*2+1)*130];
        const ull* w0p = (const ull*)&sW[(tx    )*130];
        const ull* w1p = (const ull*)&sW[(tx+16 )*130];
        const ull* w2p = (const ull*)&sW[(tx+32 )*130];
        #pragma unroll 8
        for (int k2=0;k2<64;k2++){
            ull a0=a0p[k2], a1=a1p[k2];
            ull b0=w0p[k2], b1=w1p[k2], b2=w2p[k2];
            ffma2(acc[0][0],a0,b0); ffma2(acc[0][1],a0,b1); ffma2(acc[0][2],a0,b2);
            ffma2(acc[1][0],a1,b0); ffma2(acc[1][1],a1,b1); ffma2(acc[1][2],a1,b2);
        }
        __syncthreads();
    }
    #pragma unroll
    for (int i=0;i<2;i++){
        int rr = r0 + ty*2 + i;
        float* dp = g_dblp[kh] + (size_t)rr*48;
        float2 v0=upk2(acc[i][0]), v1=upk2(acc[i][1]), v2=upk2(acc[i][2]);
        dp[tx]    = v0.x+v0.y;
        dp[tx+16] = v1.x+v1.y;
        dp[tx+32] = v2.x+v2.y;
    }
}

// ---------------- dt2: tiled dt = softplus(dtr @ Wdt^T + b) ----------------
__global__ __launch_bounds__(256) void dt2(const float* __restrict__ Wdt,
                                           const float* __restrict__ bdt, int lay){
    __shared__ float sd[64][17];
    __shared__ float sw[16][128];
    __shared__ float sb[128];

    int tid = threadIdx.x;
    int d0  = blockIdx.x*128;
    int r0  = blockIdx.y*64;
    int si  = r0 >> 10;
    int wl  = lay + 2*(si>>1);

    {
        int r = tid>>2, q4 = (tid&3)*4;
        const float4 a = *(const float4*)(g_dblp[0] + (size_t)(r0+r)*48 + q4);
        const float4 b = *(const float4*)(g_dblp[1] + (size_t)(r0+r)*48 + q4);
        sd[r][q4+0]=a.x+b.x; sd[r][q4+1]=a.y+b.y; sd[r][q4+2]=a.z+b.z; sd[r][q4+3]=a.w+b.w;
    }
    #pragma unroll
    for (int it=0; it<2; it++){
        int i = tid + it*256;
        int j = i>>2, q4 = (i&3)*4;
        float4 v = *(const float4*)(Wdt + (size_t)(wl*DI + d0 + j)*RK + q4);
        sw[q4+0][j]=v.x; sw[q4+1][j]=v.y; sw[q4+2][j]=v.z; sw[q4+3][j]=v.w;
    }
    if (tid < 128) sb[tid] = bdt[wl*DI + d0 + tid];
    __syncthreads();

    int td = tid & 127, half = tid >> 7;
    float w[16];
    #pragma unroll
    for (int q=0;q<16;q++) w[q] = sw[q][td];
    float bias = sb[td];
    #pragma unroll 4
    for (int rr=0; rr<32; rr++){
        int r = half*32 + rr;
        float acc = bias;
        #pragma unroll
        for (int q=0;q<16;q++) acc = fmaf(sd[r][q], w[q], acc);
        g_dt[(size_t)(r0+r)*DI + d0 + td] = softplus_f(acc);
    }
}

// ---------------- scan phase 1 (256 thr, s-split x2) ----------------
__global__ __launch_bounds__(256) void scan_phase1(int lay){
    int tid = threadIdx.x;
    int dl  = tid & 127;
    int sh  = tid >> 7;
    int d0b = blockIdx.x*128;
    int d   = d0b + dl;
    int ch  = blockIdx.y;
    int si  = blockIdx.z;
    int wl  = lay + 2*(si>>1);
    __shared__ float sdt[CLEN][128];
    __shared__ float sxc[CLEN][128];
    __shared__ float sB[CLEN][DS];
    int rbase = si*L + ch*CLEN;
    #pragma unroll
    for (int it=0; it<CLEN/8; it++){
        int i  = tid + it*256;
        int ll = i >> 5, dd = (i & 31)*4;
        *(float4*)&sdt[ll][dd] = *(const float4*)(g_dt + (size_t)(rbase+ll)*DI + d0b + dd);
        *(float4*)&sxc[ll][dd] = *(const float4*)(g_xc + (size_t)(rbase+ll)*DI + d0b + dd);
    }
    #pragma unroll
    for (int i=tid; i<CLEN*DS; i+=256){
        int ll = i>>4, s = i&15;
        size_t off = (size_t)(rbase+ll)*48 + 16 + s;
        sB[ll][s] = g_dblp[0][off] + g_dblp[1][off];
    }
    __syncthreads();
    float A2[8], h[8];
    {
        const float4* ap = (const float4*)(g_A2 + (size_t)(wl*DI+d)*DS + sh*8);
        float4 v0 = ap[0], v1 = ap[1];
        A2[0]=v0.x; A2[1]=v0.y; A2[2]=v0.z; A2[3]=v0.w;
        A2[4]=v1.x; A2[5]=v1.y; A2[6]=v1.z; A2[7]=v1.w;
    }
    #pragma unroll
    for (int s=0;s<8;s++) h[s]=0.f;
    float sdtacc = 0.f;
    #pragma unroll 4
    for (int ll=0; ll<CLEN; ll++){
        float dtc = sdt[ll][dl];
        float xcv = sxc[ll][dl];
        float dtx = dtc*xcv;
        sdtacc += dtc;
        #pragma unroll
        for (int s=0;s<8;s++){
            float dA = ex2f(dtc*A2[s]);
            h[s] = fmaf(dA, h[s], dtx*sB[ll][sh*8+s]);
        }
    }
    size_t ob = ((size_t)(si*DI + d)*CH + ch)*DS + sh*8;
    float P[8];
    #pragma unroll
    for (int s=0;s<8;s++) P[s] = ex2f(sdtacc*A2[s]);
    *(float4*)(g_H+ob)   = make_float4(h[0],h[1],h[2],h[3]);
    *(float4*)(g_H+ob+4) = make_float4(h[4],h[5],h[6],h[7]);
    *(float4*)(g_P+ob)   = make_float4(P[0],P[1],P[2],P[3]);
    *(float4*)(g_P+ob+4) = make_float4(P[4],P[5],P[6],P[7]);
}

// ---------------- scan combine ----------------
__global__ void scan_comb(){
    int idx = blockIdx.x*blockDim.x + threadIdx.x;
    int s = idx & 15;
    int t = idx >> 4;
    size_t base = (size_t)t*CH*DS + s;
    float run = 0.f;
    #pragma unroll 8
    for (int c=0;c<CH;c++){
        size_t p = base + (size_t)c*DS;
        float he = g_H[p], pe = g_P[p];
        g_H[p] = run;
        run = fmaf(pe, run, he);
    }
}

// ---------------- scan phase 2 (256 thr, s-split in-warp) ----------------
__global__ __launch_bounds__(256) void scan_phase2(const float* __restrict__ Dp, int lay){
    int tid  = threadIdx.x;
    int w    = tid >> 5, lane = tid & 31;
    int sh   = lane >> 4;
    int dl   = w*16 + (lane & 15);
    int d0b  = blockIdx.x*128;
    int d    = d0b + dl;
    int ch   = blockIdx.y;
    int si   = blockIdx.z;
    int wl   = lay + 2*(si>>1);
    __shared__ float sdt[CLEN][128];
    __shared__ float sxc[CLEN][128];
    __shared__ float sB[CLEN][DS];
    __shared__ float sC[CLEN][DS];
    int rbase = si*L + ch*CLEN;
    #pragma unroll
    for (int it=0; it<CLEN/8; it++){
        int i  = tid + it*256;
        int ll = i >> 5, dd = (i & 31)*4;
        *(float4*)&sdt[ll][dd] = *(const float4*)(g_dt + (size_t)(rbase+ll)*DI + d0b + dd);
        *(float4*)&sxc[ll][dd] = *(const float4*)(g_xc + (size_t)(rbase+ll)*DI + d0b + dd);
    }
    #pragma unroll
    for (int i=tid; i<CLEN*DS; i+=256){
        int ll = i>>4, s = i&15;
        size_t off = (size_t)(rbase+ll)*48 + 16 + s;
        sB[ll][s] = g_dblp[0][off]    + g_dblp[1][off];
        sC[ll][s] = g_dblp[0][off+16] + g_dblp[1][off+16];
    }
    __syncthreads();
    float A2[8], h[8];
    size_t ib = ((size_t)(si*DI + d)*CH + ch)*DS + sh*8;
    {
        const float4* ap = (const float4*)(g_A2 + (size_t)(wl*DI+d)*DS + sh*8);
        float4 v0 = ap[0], v1 = ap[1];
        A2[0]=v0.x; A2[1]=v0.y; A2[2]=v0.z; A2[3]=v0.w;
        A2[4]=v1.x; A2[5]=v1.y; A2[6]=v1.z; A2[7]=v1.w;
        float4 h0 = *(const float4*)(g_H+ib);
        float4 h1 = *(const float4*)(g_H+ib+4);
        h[0]=h0.x; h[1]=h0.y; h[2]=h0.z; h[3]=h0.w;
        h[4]=h1.x; h[5]=h1.y; h[6]=h1.z; h[7]=h1.w;
    }
    float Dd = Dp[wl*DI + d];
    #pragma unroll 4
    for (int ll=0; ll<CLEN; ll++){
        int r = rbase + ll;
        float dtc = sdt[ll][dl];
        float xcv = sxc[ll][dl];
        float z   = g_xz[(size_t)r*(2*DI) + DI + d];
        float dtx = dtc*xcv;
        float y0=0.f, y1=0.f;
        #pragma unroll
        for (int s=0;s<8;s++){
            float dA = ex2f(dtc*A2[s]);
            h[s] = fmaf(dA, h[s], dtx*sB[ll][sh*8+s]);
            if (s & 1) y1 = fmaf(h[s], sC[ll][sh*8+s], y1);
            else       y0 = fmaf(h[s], sC[ll][sh*8+s], y0);
        }
        float yp = y0 + y1;
        float y  = yp + __shfl_xor_sync(0xffffffffu, yp, 16);
        if (sh == 0){
            y = fmaf(xcv, Dd, y);
            y *= silu_f(z);
            g_y[(size_t)r*DI + d] = y;
        }
    }
}

// ---------------- launch ----------------
extern "C" void kernel_launch(void* const* d_in, const int* in_sizes, int n_in,
                              void* d_out, int out_size)
{
    (void)in_sizes; (void)n_in; (void)out_size;
    const float* x        = (const float*)d_in[0];
    const float* in_proj  = (const float*)d_in[1];
    const float* conv_w   = (const float*)d_in[2];
    const float* conv_b   = (const float*)d_in[3];
    const float* x_proj   = (const float*)d_in[4];
    const float* dt_proj  = (const float*)d_in[5];
    const float* dt_bias  = (const float*)d_in[6];
    const float* A_log    = (const float*)d_in[7];
    const float* Dp       = (const float*)d_in[8];
    const float* out_proj = (const float*)d_in[9];
    float* out = (float*)d_out;

    a2_kernel<<<4*DI*DS/256, 256>>>(A_log);

    for (int lay = 0; lay < 2; lay++){
        int ain  = lay ? 1 : 3;        // layer0 reads x with prep-remap, layer1 reads g_a1
        int cout = lay ? 3 : 1;        // layer1 writes out with final-remap, layer0 -> g_a1

        // xz = act @ in_proj^T   (N=1024, K=256), 128x128 tiles
        gemm2<128,128><<<dim3((2*DI)/128, ROWS/128), 256>>>(ain, in_proj, 2, 2*DI, DM, lay, x, nullptr);
        xproj3<<<dim3(ROWS/32, 2), 256>>>(x_proj, conv_w, conv_b, lay);
        dt2<<<dim3(DI/128, ROWS/64), 256>>>(dt_proj, dt_bias, lay);
        scan_phase1<<<dim3(DI/128, CH, NSEQ), 256>>>(lay);
        scan_comb<<<NSEQ*DI*DS/256, 256>>>();
        scan_phase2<<<dim3(DI/128, CH, NSEQ), 256>>>(Dp, lay);
        // act_out = y @ out_proj^T  (N=256, K=512), 64x64 tiles
        gemm2<64,64><<<dim3(DM/64, ROWS/64), 256>>>(2, out_proj, cout, DM, DI, lay, nullptr, out);
    }
}